// round 1
// baseline (speedup 1.0000x reference)
#include <cuda_runtime.h>
#include <cstdint>

#define EPSBN 1e-5f
typedef unsigned long long u64;

// ---------- packed f32x2 helpers (sm_100+ PTX) ----------
__device__ __forceinline__ u64 pack2(float lo, float hi){
  u64 r; asm("mov.b64 %0, {%1,%2};" : "=l"(r) : "f"(lo), "f"(hi)); return r;
}
__device__ __forceinline__ void unpack2(u64 v, float& lo, float& hi){
  asm("mov.b64 {%0,%1}, %2;" : "=f"(lo), "=f"(hi) : "l"(v));
}
__device__ __forceinline__ u64 fma2(u64 a, u64 b, u64 c){
  u64 d; asm("fma.rn.f32x2 %0, %1, %2, %3;" : "=l"(d) : "l"(a), "l"(b), "l"(c)); return d;
}

// ---------- fused (BN-folded) weights in device scratch ----------
// layout (floats): A0[3*64], C0[64], A1[64*128], C1[128], A2[128*256], C2[256],
//                  A3[256*64], C3[64]
#define OFF_A0 0
#define OFF_C0 192
#define OFF_A1 256
#define OFF_C1 8448
#define OFF_A2 8576
#define OFF_C2 41344
#define OFF_A3 41600
#define OFF_C3 57984
#define FUSED_TOTAL 58048
__device__ float gF[FUSED_TOTAL];

__global__ void prep_kernel(
  const float* __restrict__ bn0_g, const float* __restrict__ bn0_b,
  const float* __restrict__ bn0_m, const float* __restrict__ bn0_v,
  const float* __restrict__ bn1_g, const float* __restrict__ bn1_b,
  const float* __restrict__ bn1_m, const float* __restrict__ bn1_v,
  const float* __restrict__ bn2_g, const float* __restrict__ bn2_b,
  const float* __restrict__ bn2_m, const float* __restrict__ bn2_v,
  const float* __restrict__ bn3_g, const float* __restrict__ bn3_b,
  const float* __restrict__ bn3_m, const float* __restrict__ bn3_v,
  const float* __restrict__ W0, const float* __restrict__ b0,
  const float* __restrict__ W1, const float* __restrict__ b1,
  const float* __restrict__ W2, const float* __restrict__ b2,
  const float* __restrict__ W3, const float* __restrict__ b3)
{
  int e = blockIdx.x*blockDim.x + threadIdx.x;
  if (e < 3*64) {
    int k = e/64, j = e%64;
    float s0 = bn0_g[k]*rsqrtf(bn0_v[k]+EPSBN);
    float s1 = bn1_g[j]*rsqrtf(bn1_v[j]+EPSBN);
    gF[OFF_A0+e] = s0*W0[e]*s1;
  }
  if (e < 64) {
    float s1 = bn1_g[e]*rsqrtf(bn1_v[e]+EPSBN);
    float t1 = bn1_b[e]-bn1_m[e]*s1;
    float acc = b0[e];
    for (int k=0;k<3;k++){
      float s0 = bn0_g[k]*rsqrtf(bn0_v[k]+EPSBN);
      float t0 = bn0_b[k]-bn0_m[k]*s0;
      acc += t0*W0[k*64+e];
    }
    gF[OFF_C0+e] = acc*s1+t1;
  }
  if (e < 64*128) {
    int j = e%128;
    float s2 = bn2_g[j]*rsqrtf(bn2_v[j]+EPSBN);
    gF[OFF_A1+e] = W1[e]*s2;
  }
  if (e < 128) {
    float s2 = bn2_g[e]*rsqrtf(bn2_v[e]+EPSBN);
    gF[OFF_C1+e] = b1[e]*s2 + bn2_b[e]-bn2_m[e]*s2;
  }
  if (e < 128*256) {
    int j = e%256;
    float s3 = bn3_g[j]*rsqrtf(bn3_v[j]+EPSBN);
    gF[OFF_A2+e] = W2[e]*s3;
  }
  if (e < 256) {
    float s3 = bn3_g[e]*rsqrtf(bn3_v[e]+EPSBN);
    gF[OFF_C2+e] = b2[e]*s3 + bn3_b[e]-bn3_m[e]*s3;
  }
  if (e < 256*64) gF[OFF_A3+e] = W3[e];
  if (e < 64)     gF[OFF_C3+e] = b3[e];
}

// ---------- output init / finalize ----------
#define NEG_INF_BITS 0xFF800000u

__global__ void init_kernel(uint4* __restrict__ out, int n16){
  int i = blockIdx.x*blockDim.x + threadIdx.x;
  if (i < n16){
    uint4 v = make_uint4(NEG_INF_BITS,NEG_INF_BITS,NEG_INF_BITS,NEG_INF_BITS);
    out[i] = v;
  }
}
__global__ void finalize_kernel(uint4* __restrict__ out, int n16){
  int i = blockIdx.x*blockDim.x + threadIdx.x;
  if (i < n16){
    uint4 v = out[i];
    if (v.x==NEG_INF_BITS) v.x=0u;
    if (v.y==NEG_INF_BITS) v.y=0u;
    if (v.z==NEG_INF_BITS) v.z=0u;
    if (v.w==NEG_INF_BITS) v.w=0u;
    out[i] = v;
  }
}

// ---------- main fused MLP + scatter-max ----------
#define TPB 256
#define TILE_M 128
#define GGRID 64

__device__ __forceinline__ void atomicMaxF(float* a, float v){
  if (v >= 0.0f) atomicMax((int*)a, __float_as_int(v));
  else           atomicMin((unsigned int*)a, __float_as_uint(v));
}

// One layer: sOut[128][N] = act(sIn[128][LDI(:K)] @ W[K][N] + C[N])
// Thread (tx,ty) owns points m = ty*8..ty*8+7, cols n = tx*TN..tx*TN+TN-1.
template<int K,int N,int TN,int LDI,bool RELU>
__device__ __forceinline__ void gemm_layer(const float* __restrict__ gW,
    const float* __restrict__ gC, const float* sIn, float* sOut, int tx, int ty)
{
  u64 acc[8][TN/2];
  #pragma unroll
  for (int j=0;j<TN;j+=4){
    float4 c4 = *(const float4*)(gC + tx*TN + j);
    #pragma unroll
    for (int i=0;i<8;i++){ acc[i][j/2]=pack2(c4.x,c4.y); acc[i][j/2+1]=pack2(c4.z,c4.w); }
  }
  const float* wp = gW + tx*TN;
  #pragma unroll 2
  for (int k=0;k<K;k++){
    u64 bfr[TN/2];
    #pragma unroll
    for (int j=0;j<TN;j+=4){
      float4 w4 = *(const float4*)(wp + j);
      bfr[j/2]=pack2(w4.x,w4.y); bfr[j/2+1]=pack2(w4.z,w4.w);
    }
    wp += N;
    #pragma unroll
    for (int i=0;i<8;i++){
      float a = sIn[(ty*8+i)*LDI + k];
      u64 a2 = pack2(a,a);
      #pragma unroll
      for (int j=0;j<TN/2;j++) acc[i][j]=fma2(a2,bfr[j],acc[i][j]);
    }
  }
  #pragma unroll
  for (int i=0;i<8;i++){
    int m = ty*8+i;
    #pragma unroll
    for (int j=0;j<TN/2;j++){
      float lo,hi; unpack2(acc[i][j],lo,hi);
      if (RELU){ lo=fmaxf(lo,0.f); hi=fmaxf(hi,0.f); }
      sOut[m*N + tx*TN + 2*j  ] = lo;
      sOut[m*N + tx*TN + 2*j+1] = hi;
    }
  }
}

// smem (floats): sX[128*4] @0, sH1[128*64] @512, sH2[128*128] @8704,
//                sH3[128*256] @25088, sSeg[128 ints] @57856  -> 57984 fl = 231936 B
__global__ void __launch_bounds__(TPB,1) mlp_kernel(
    const float* __restrict__ pt_fea, const int* __restrict__ pt_ind,
    float* __restrict__ out, int P, int Nn)
{
  extern __shared__ float sm[];
  float* sX  = sm;
  float* sH1 = sm + 512;
  float* sH2 = sm + 8704;
  float* sH3 = sm + 25088;
  int*   sSeg = (int*)(sm + 57856);

  int t = threadIdx.x, tx = t & 15, ty = t >> 4;
  int base = blockIdx.x * TILE_M;

  if (t < TILE_M) {
    int p = base + t;
    float x0=0.f,x1=0.f,x2=0.f; int seg=0;
    if (p < P) {
      x0 = pt_fea[p*3+0]; x1 = pt_fea[p*3+1]; x2 = pt_fea[p*3+2];
      int ix = pt_ind[p*3+0], iy = pt_ind[p*3+1], iz = pt_ind[p*3+2];
      int b = p / Nn;
      seg = ((b*GGRID + iz)*GGRID + iy)*GGRID + ix;
    }
    sX[t*4+0]=x0; sX[t*4+1]=x1; sX[t*4+2]=x2; sX[t*4+3]=0.f;
    sSeg[t]=seg;
  }
  __syncthreads();
  gemm_layer<3,  64, 4,  4, true >(gF+OFF_A0, gF+OFF_C0, sX , sH1, tx, ty);
  __syncthreads();
  gemm_layer<64, 128,8, 64, true >(gF+OFF_A1, gF+OFF_C1, sH1, sH2, tx, ty);
  __syncthreads();
  gemm_layer<128,256,16,128,true >(gF+OFF_A2, gF+OFF_C2, sH2, sH3, tx, ty);
  __syncthreads();

  // Layer 4 (256 -> 64) + scatter-max epilogue
  {
    u64 acc[8][2];
    float4 c4 = *(const float4*)(gF+OFF_C3 + tx*4);
    #pragma unroll
    for (int i=0;i<8;i++){ acc[i][0]=pack2(c4.x,c4.y); acc[i][1]=pack2(c4.z,c4.w); }
    const float* wp = gF + OFF_A3 + tx*4;
    #pragma unroll 2
    for (int k=0;k<256;k++){
      float4 w4 = *(const float4*)wp; wp += 64;
      u64 b0p=pack2(w4.x,w4.y), b1p=pack2(w4.z,w4.w);
      #pragma unroll
      for (int i=0;i<8;i++){
        float a = sH3[(ty*8+i)*256 + k];
        u64 a2 = pack2(a,a);
        acc[i][0]=fma2(a2,b0p,acc[i][0]);
        acc[i][1]=fma2(a2,b1p,acc[i][1]);
      }
    }
    #pragma unroll
    for (int i=0;i<8;i++){
      int m = ty*8+i; int p = base + m;
      if (p < P){
        float* dst = out + (size_t)sSeg[m]*64 + tx*4;
        float v0,v1,v2,v3;
        unpack2(acc[i][0],v0,v1); unpack2(acc[i][1],v2,v3);
        atomicMaxF(dst+0,v0); atomicMaxF(dst+1,v1);
        atomicMaxF(dst+2,v2); atomicMaxF(dst+3,v3);
      }
    }
  }
}

// ---------- launch ----------
extern "C" void kernel_launch(void* const* d_in, const int* in_sizes, int n_in,
                              void* d_out, int out_size)
{
  const float* pt_fea = (const float*)d_in[0];
  const int*   pt_ind = (const int*)d_in[1];
  const float* a[24];
  for (int i=0;i<24;i++) a[i] = (const float*)d_in[2+i];

  int P  = in_sizes[0] / 3;   // 500000
  int Nn = P / 2;             // points per batch (B=2)

  prep_kernel<<<(32768+255)/256, 256>>>(
    a[0],a[1],a[2],a[3], a[4],a[5],a[6],a[7],
    a[8],a[9],a[10],a[11], a[12],a[13],a[14],a[15],
    a[16],a[17], a[18],a[19], a[20],a[21], a[22],a[23]);

  int n16 = out_size / 4;     // uint4 count
  init_kernel<<<(n16+255)/256, 256>>>((uint4*)d_out, n16);

  cudaFuncSetAttribute(mlp_kernel, cudaFuncAttributeMaxDynamicSharedMemorySize, 231936);
  int blocks = (P + TILE_M - 1) / TILE_M;
  mlp_kernel<<<blocks, TPB, 231936>>>(pt_fea, pt_ind, (float*)d_out, P, Nn);

  finalize_kernel<<<(n16+255)/256, 256>>>((uint4*)d_out, n16);
}

// round 2
// speedup vs baseline: 1.0662x; 1.0662x over previous
#include <cuda_runtime.h>
#include <cstdint>

#define EPSBN 1e-5f
typedef unsigned long long u64;

// ---------- packed f32x2 helpers (sm_100+ PTX) ----------
__device__ __forceinline__ u64 pack2(float lo, float hi){
  u64 r; asm("mov.b64 %0, {%1,%2};" : "=l"(r) : "f"(lo), "f"(hi)); return r;
}
__device__ __forceinline__ void unpack2(u64 v, float& lo, float& hi){
  asm("mov.b64 {%0,%1}, %2;" : "=f"(lo), "=f"(hi) : "l"(v));
}
__device__ __forceinline__ u64 fma2(u64 a, u64 b, u64 c){
  u64 d; asm("fma.rn.f32x2 %0, %1, %2, %3;" : "=l"(d) : "l"(a), "l"(b), "l"(c)); return d;
}

// ---------- fused (BN-folded) weights in device scratch ----------
// Weights stored INTERLEAVED per layer for coalesced per-thread float4 loads:
//   element (k, n) -> [ ((k*TNQ + (n%TN)/4)*THN + n/TN)*4 + n%4 ]
#define OFF_A0 0
#define OFF_C0 192
#define OFF_A1 256
#define OFF_C1 8448
#define OFF_A2 8576
#define OFF_C2 41344
#define OFF_A3 41600
#define OFF_C3 57984
#define FUSED_TOTAL 58048
__device__ float gF[FUSED_TOTAL];

// layer tiling configs (must match gemm_layer template args below)
#define L1_TN 4
#define L2_TN 8
#define L3_TN 16
#define L4_TN 8
#define L1_THN 16
#define L2_THN 16
#define L3_THN 16
#define L4_THN 8

__host__ __device__ __forceinline__ int ilv(int k, int n, int TN, int THN){
  int TNQ = TN/4;
  return ((k*TNQ + (n%TN)/4)*THN + n/TN)*4 + (n%4);
}

__global__ void prep_kernel(
  const float* __restrict__ bn0_g, const float* __restrict__ bn0_b,
  const float* __restrict__ bn0_m, const float* __restrict__ bn0_v,
  const float* __restrict__ bn1_g, const float* __restrict__ bn1_b,
  const float* __restrict__ bn1_m, const float* __restrict__ bn1_v,
  const float* __restrict__ bn2_g, const float* __restrict__ bn2_b,
  const float* __restrict__ bn2_m, const float* __restrict__ bn2_v,
  const float* __restrict__ bn3_g, const float* __restrict__ bn3_b,
  const float* __restrict__ bn3_m, const float* __restrict__ bn3_v,
  const float* __restrict__ W0, const float* __restrict__ b0,
  const float* __restrict__ W1, const float* __restrict__ b1,
  const float* __restrict__ W2, const float* __restrict__ b2,
  const float* __restrict__ W3, const float* __restrict__ b3)
{
  int e = blockIdx.x*blockDim.x + threadIdx.x;
  if (e < 3*64) {
    int k = e/64, n = e%64;
    float s0 = bn0_g[k]*rsqrtf(bn0_v[k]+EPSBN);
    float s1 = bn1_g[n]*rsqrtf(bn1_v[n]+EPSBN);
    gF[OFF_A0 + ilv(k,n,L1_TN,L1_THN)] = s0*W0[e]*s1;
  }
  if (e < 64) {
    float s1 = bn1_g[e]*rsqrtf(bn1_v[e]+EPSBN);
    float t1 = bn1_b[e]-bn1_m[e]*s1;
    float acc = b0[e];
    for (int k=0;k<3;k++){
      float s0 = bn0_g[k]*rsqrtf(bn0_v[k]+EPSBN);
      float t0 = bn0_b[k]-bn0_m[k]*s0;
      acc += t0*W0[k*64+e];
    }
    gF[OFF_C0+e] = acc*s1+t1;
  }
  if (e < 64*128) {
    int k = e/128, n = e%128;
    float s2 = bn2_g[n]*rsqrtf(bn2_v[n]+EPSBN);
    gF[OFF_A1 + ilv(k,n,L2_TN,L2_THN)] = W1[e]*s2;
  }
  if (e < 128) {
    float s2 = bn2_g[e]*rsqrtf(bn2_v[e]+EPSBN);
    gF[OFF_C1+e] = b1[e]*s2 + bn2_b[e]-bn2_m[e]*s2;
  }
  if (e < 128*256) {
    int k = e/256, n = e%256;
    float s3 = bn3_g[n]*rsqrtf(bn3_v[n]+EPSBN);
    gF[OFF_A2 + ilv(k,n,L3_TN,L3_THN)] = W2[e]*s3;
  }
  if (e < 256) {
    float s3 = bn3_g[e]*rsqrtf(bn3_v[e]+EPSBN);
    gF[OFF_C2+e] = b2[e]*s3 + bn3_b[e]-bn3_m[e]*s3;
  }
  if (e < 256*64) {
    int k = e/64, n = e%64;
    gF[OFF_A3 + ilv(k,n,L4_TN,L4_THN)] = W3[e];
  }
  if (e < 64) gF[OFF_C3+e] = b3[e];
}

// ---------- output init / finalize ----------
#define NEG_INF_BITS 0xFF800000u

__global__ void init_kernel(uint4* __restrict__ out, int n16){
  int i = blockIdx.x*blockDim.x + threadIdx.x;
  if (i < n16){
    out[i] = make_uint4(NEG_INF_BITS,NEG_INF_BITS,NEG_INF_BITS,NEG_INF_BITS);
  }
}
__global__ void finalize_kernel(uint4* __restrict__ out, int n16){
  int i = blockIdx.x*blockDim.x + threadIdx.x;
  if (i < n16){
    uint4 v = out[i];
    if (v.x==NEG_INF_BITS) v.x=0u;
    if (v.y==NEG_INF_BITS) v.y=0u;
    if (v.z==NEG_INF_BITS) v.z=0u;
    if (v.w==NEG_INF_BITS) v.w=0u;
    out[i] = v;
  }
}

// ---------- main fused MLP + scatter-max ----------
#define TPB 256
#define TILE_M 128
#define GGRID 64

__device__ __forceinline__ void atomicMaxF(float* a, float v){
  if (v >= 0.0f) atomicMax((int*)a, __float_as_int(v));
  else           atomicMin((unsigned int*)a, __float_as_uint(v));
}

// One layer: sOut[128][LDO(:N)] = act(sIn[128][LDI(:K)] @ W[K][N] + C[N])
// Thread t: tx = t % (N/TN) owns cols tx*TN..+TN-1, ty = t / (N/TN) owns
// rows ty*TM..+TM-1. Weights are read from the interleaved layout.
template<int K,int N,int TN,int TM,int LDI,int LDO,bool RELU>
__device__ __forceinline__ void gemm_layer(const float* __restrict__ gW,
    const float* __restrict__ gC, const float* sIn, float* sOut, int t)
{
  constexpr int THN = N/TN;
  constexpr int TNQ = TN/4;
  int tx = t % THN, ty = t / THN;
  u64 acc[TM][TN/2];
  #pragma unroll
  for (int j=0;j<TNQ;j++){
    float4 c4 = *(const float4*)(gC + tx*TN + j*4);
    #pragma unroll
    for (int i=0;i<TM;i++){ acc[i][2*j]=pack2(c4.x,c4.y); acc[i][2*j+1]=pack2(c4.z,c4.w); }
  }
  #pragma unroll 2
  for (int k=0;k<K;k++){
    u64 w[TN/2];
    #pragma unroll
    for (int j=0;j<TNQ;j++){
      float4 w4 = *(const float4*)(gW + ((k*TNQ+j)*THN + tx)*4);
      w[2*j]=pack2(w4.x,w4.y); w[2*j+1]=pack2(w4.z,w4.w);
    }
    #pragma unroll
    for (int i=0;i<TM;i++){
      float a = sIn[(ty*TM+i)*LDI + k];
      u64 a2 = pack2(a,a);
      #pragma unroll
      for (int j=0;j<TN/2;j++) acc[i][j]=fma2(a2,w[j],acc[i][j]);
    }
  }
  #pragma unroll
  for (int i=0;i<TM;i++){
    int m = ty*TM+i;
    #pragma unroll
    for (int j=0;j<TN/2;j++){
      float lo,hi; unpack2(acc[i][j],lo,hi);
      if (RELU){ lo=fmaxf(lo,0.f); hi=fmaxf(hi,0.f); }
      sOut[m*LDO + tx*TN + 2*j  ] = lo;
      sOut[m*LDO + tx*TN + 2*j+1] = hi;
    }
  }
}

// smem layout (floats), padded strides for conflict-free LDS:
//   sH2 [128][130] @ 0          (16640)
//   sH3 [128][258] @ 16640      (33024)  -- overlaps dead sX/sH1 region
//   sX  [128][4]   @ 16640      (512, dead after L1)
//   sH1 [128][66]  @ 17152      (8448, dead after L2)
//   sSeg[128] ints @ 49664
// total 49792 floats = 199168 B
#define SM_H2   0
#define SM_H3   16640
#define SM_X    16640
#define SM_H1   17152
#define SM_SEG  49664
#define SM_TOTALF 49792

__global__ void __launch_bounds__(TPB,1) mlp_kernel(
    const float* __restrict__ pt_fea, const int* __restrict__ pt_ind,
    float* __restrict__ out, int P, int Nn)
{
  extern __shared__ float sm[];
  float* sH2 = sm + SM_H2;
  float* sH3 = sm + SM_H3;
  float* sX  = sm + SM_X;
  float* sH1 = sm + SM_H1;
  int*   sSeg = (int*)(sm + SM_SEG);

  int t = threadIdx.x;
  int base = blockIdx.x * TILE_M;

  if (t < TILE_M) {
    int p = base + t;
    float x0=0.f,x1=0.f,x2=0.f; int seg=0;
    if (p < P) {
      x0 = pt_fea[p*3+0]; x1 = pt_fea[p*3+1]; x2 = pt_fea[p*3+2];
      int ix = pt_ind[p*3+0], iy = pt_ind[p*3+1], iz = pt_ind[p*3+2];
      int b = p / Nn;
      seg = ((b*GGRID + iz)*GGRID + iy)*GGRID + ix;
    }
    sX[t*4+0]=x0; sX[t*4+1]=x1; sX[t*4+2]=x2; sX[t*4+3]=0.f;
    sSeg[t]=seg;
  }
  __syncthreads();
  gemm_layer<3,  64, L1_TN,8, 4,  66, true>(gF+OFF_A0, gF+OFF_C0, sX , sH1, t);
  __syncthreads();
  gemm_layer<64, 128,L2_TN,8, 66, 130,true>(gF+OFF_A1, gF+OFF_C1, sH1, sH2, t);
  __syncthreads();
  gemm_layer<128,256,L3_TN,8, 130,258,true>(gF+OFF_A2, gF+OFF_C2, sH2, sH3, t);
  __syncthreads();

  // Layer 4 (256 -> 64), TN=8 / TM=4, fused scatter-max epilogue
  {
    constexpr int TN = L4_TN, THN = L4_THN, TM = 4, TNQ = TN/4;
    int tx = t % THN, ty = t / THN;
    u64 acc[TM][TN/2];
    #pragma unroll
    for (int j=0;j<TNQ;j++){
      float4 c4 = *(const float4*)(gF+OFF_C3 + tx*TN + j*4);
      #pragma unroll
      for (int i=0;i<TM;i++){ acc[i][2*j]=pack2(c4.x,c4.y); acc[i][2*j+1]=pack2(c4.z,c4.w); }
    }
    const float* gW = gF + OFF_A3;
    #pragma unroll 2
    for (int k=0;k<256;k++){
      u64 w[TN/2];
      #pragma unroll
      for (int j=0;j<TNQ;j++){
        float4 w4 = *(const float4*)(gW + ((k*TNQ+j)*THN + tx)*4);
        w[2*j]=pack2(w4.x,w4.y); w[2*j+1]=pack2(w4.z,w4.w);
      }
      #pragma unroll
      for (int i=0;i<TM;i++){
        float a = sH3[(ty*TM+i)*258 + k];
        u64 a2 = pack2(a,a);
        #pragma unroll
        for (int j=0;j<TN/2;j++) acc[i][j]=fma2(a2,w[j],acc[i][j]);
      }
    }
    #pragma unroll
    for (int i=0;i<TM;i++){
      int m = ty*TM+i; int p = base + m;
      if (p < P){
        float* dst = out + (size_t)sSeg[m]*64 + tx*TN;
        #pragma unroll
        for (int j=0;j<TN/2;j++){
          float lo,hi; unpack2(acc[i][j],lo,hi);
          atomicMaxF(dst+2*j,   lo);
          atomicMaxF(dst+2*j+1, hi);
        }
      }
    }
  }
}

// ---------- launch ----------
extern "C" void kernel_launch(void* const* d_in, const int* in_sizes, int n_in,
                              void* d_out, int out_size)
{
  const float* pt_fea = (const float*)d_in[0];
  const int*   pt_ind = (const int*)d_in[1];
  const float* a[24];
  for (int i=0;i<24;i++) a[i] = (const float*)d_in[2+i];

  int P  = in_sizes[0] / 3;   // 500000
  int Nn = P / 2;             // points per batch (B=2)

  prep_kernel<<<(32768+255)/256, 256>>>(
    a[0],a[1],a[2],a[3], a[4],a[5],a[6],a[7],
    a[8],a[9],a[10],a[11], a[12],a[13],a[14],a[15],
    a[16],a[17], a[18],a[19], a[20],a[21], a[22],a[23]);

  int n16 = out_size / 4;     // uint4 count
  init_kernel<<<(n16+255)/256, 256>>>((uint4*)d_out, n16);

  cudaFuncSetAttribute(mlp_kernel, cudaFuncAttributeMaxDynamicSharedMemorySize, SM_TOTALF*4);
  int blocks = (P + TILE_M - 1) / TILE_M;
  mlp_kernel<<<blocks, TPB, SM_TOTALF*4>>>(pt_fea, pt_ind, (float*)d_out, P, Nn);

  finalize_kernel<<<(n16+255)/256, 256>>>((uint4*)d_out, n16);
}

// round 3
// speedup vs baseline: 1.4358x; 1.3466x over previous
#include <cuda_runtime.h>
#include <cstdint>

#define EPSBN 1e-5f
typedef unsigned long long u64;

// ---------- packed f32x2 helpers (sm_100+ PTX) ----------
__device__ __forceinline__ u64 pack2(float lo, float hi){
  u64 r; asm("mov.b64 %0, {%1,%2};" : "=l"(r) : "f"(lo), "f"(hi)); return r;
}
__device__ __forceinline__ void unpack2(u64 v, float& lo, float& hi){
  asm("mov.b64 {%0,%1}, %2;" : "=f"(lo), "=f"(hi) : "l"(v));
}
__device__ __forceinline__ u64 fma2(u64 a, u64 b, u64 c){
  u64 d; asm("fma.rn.f32x2 %0, %1, %2, %3;" : "=l"(d) : "l"(a), "l"(b), "l"(c)); return d;
}
__device__ __forceinline__ void cpa16(uint32_t dst, const float* src){
  asm volatile("cp.async.ca.shared.global [%0], [%1], 16;" :: "r"(dst), "l"(src));
}

// ---------- fused (BN-folded) weights in device scratch ----------
#define OFF_A0 0
#define OFF_C0 192
#define OFF_A1 256
#define OFF_C1 8448
#define OFF_A2 8576
#define OFF_C2 41344
#define OFF_A3 41600
#define OFF_C3 57984
#define FUSED_TOTAL 58048
__device__ float gF[FUSED_TOTAL];

// layer tiling (TN, THN) -- interleave layout depends on these
#define L1_TN 4
#define L2_TN 8
#define L3_TN 16
#define L4_TN 8
#define L1_THN 16
#define L2_THN 16
#define L3_THN 16
#define L4_THN 8

__host__ __device__ __forceinline__ int ilv(int k, int n, int TN, int THN){
  int TNQ = TN/4;
  return ((k*TNQ + (n%TN)/4)*THN + n/TN)*4 + (n%4);
}

__global__ void prep_kernel(
  const float* __restrict__ bn0_g, const float* __restrict__ bn0_b,
  const float* __restrict__ bn0_m, const float* __restrict__ bn0_v,
  const float* __restrict__ bn1_g, const float* __restrict__ bn1_b,
  const float* __restrict__ bn1_m, const float* __restrict__ bn1_v,
  const float* __restrict__ bn2_g, const float* __restrict__ bn2_b,
  const float* __restrict__ bn2_m, const float* __restrict__ bn2_v,
  const float* __restrict__ bn3_g, const float* __restrict__ bn3_b,
  const float* __restrict__ bn3_m, const float* __restrict__ bn3_v,
  const float* __restrict__ W0, const float* __restrict__ b0,
  const float* __restrict__ W1, const float* __restrict__ b1,
  const float* __restrict__ W2, const float* __restrict__ b2,
  const float* __restrict__ W3, const float* __restrict__ b3)
{
  int e = blockIdx.x*blockDim.x + threadIdx.x;
  if (e < 3*64) {
    int k = e/64, n = e%64;
    float s0 = bn0_g[k]*rsqrtf(bn0_v[k]+EPSBN);
    float s1 = bn1_g[n]*rsqrtf(bn1_v[n]+EPSBN);
    gF[OFF_A0 + ilv(k,n,L1_TN,L1_THN)] = s0*W0[e]*s1;
  }
  if (e < 64) {
    float s1 = bn1_g[e]*rsqrtf(bn1_v[e]+EPSBN);
    float t1 = bn1_b[e]-bn1_m[e]*s1;
    float acc = b0[e];
    for (int k=0;k<3;k++){
      float s0 = bn0_g[k]*rsqrtf(bn0_v[k]+EPSBN);
      float t0 = bn0_b[k]-bn0_m[k]*s0;
      acc += t0*W0[k*64+e];
    }
    gF[OFF_C0+e] = acc*s1+t1;
  }
  if (e < 64*128) {
    int k = e/128, n = e%128;
    float s2 = bn2_g[n]*rsqrtf(bn2_v[n]+EPSBN);
    gF[OFF_A1 + ilv(k,n,L2_TN,L2_THN)] = W1[e]*s2;
  }
  if (e < 128) {
    float s2 = bn2_g[e]*rsqrtf(bn2_v[e]+EPSBN);
    gF[OFF_C1+e] = b1[e]*s2 + bn2_b[e]-bn2_m[e]*s2;
  }
  if (e < 128*256) {
    int k = e/256, n = e%256;
    float s3 = bn3_g[n]*rsqrtf(bn3_v[n]+EPSBN);
    gF[OFF_A2 + ilv(k,n,L3_TN,L3_THN)] = W2[e]*s3;
  }
  if (e < 256) {
    float s3 = bn3_g[e]*rsqrtf(bn3_v[e]+EPSBN);
    gF[OFF_C2+e] = b2[e]*s3 + bn3_b[e]-bn3_m[e]*s3;
  }
  if (e < 256*64) {
    int k = e/64, n = e%64;
    gF[OFF_A3 + ilv(k,n,L4_TN,L4_THN)] = W3[e];
  }
  if (e < 64) gF[OFF_C3+e] = b3[e];
}

// ---------- output init / finalize ----------
#define NEG_INF_BITS 0xFF800000u

__global__ void init_kernel(uint4* __restrict__ out, int n16){
  int i = blockIdx.x*blockDim.x + threadIdx.x;
  if (i < n16){
    out[i] = make_uint4(NEG_INF_BITS,NEG_INF_BITS,NEG_INF_BITS,NEG_INF_BITS);
  }
}
__global__ void finalize_kernel(uint4* __restrict__ out, int n16){
  int i = blockIdx.x*blockDim.x + threadIdx.x;
  if (i < n16){
    uint4 v = out[i];
    if (v.x==NEG_INF_BITS) v.x=0u;
    if (v.y==NEG_INF_BITS) v.y=0u;
    if (v.z==NEG_INF_BITS) v.z=0u;
    if (v.w==NEG_INF_BITS) v.w=0u;
    out[i] = v;
  }
}

// ---------- main fused MLP + scatter-max ----------
#define TPB 512
#define TILE_M 128
#define GGRID 64

__device__ __forceinline__ void atomicMaxF(float* a, float v){
  if (v >= 0.0f) atomicMax((int*)a, __float_as_int(v));
  else           atomicMin((unsigned int*)a, __float_as_uint(v));
}

// smem layout (floats):
//   sH2 [128][132] @ 0       (16896)
//   sH3 [128][260] @ 16896   (33280)  (overlaps dead sX/sH1 during L3/L4)
//   sX  [128][4]   @ 16896   (512, dead after L1)
//   sH1 [128][68]  @ 17408   (8704, dead after L2)
//   wBuf[4096]     @ 50176   (double buffer, 2 x 2048)
//   sSeg[128]ints  @ 54272
#define SM_H2   0
#define SM_H3   16896
#define SM_X    16896
#define SM_H1   17408
#define SM_WB   50176
#define SM_SEG  54272
#define SM_TOTALF 54400

// L1 (tiny K=3): direct weight loads from global
template<int K,int N,int TN,int TM,int LDI,int LDO,bool RELU>
__device__ __forceinline__ void gemm_direct(const float* __restrict__ gW,
    const float* __restrict__ gC, const float* sIn, float* sOut, int t)
{
  constexpr int THN = N/TN, TNQ = TN/4;
  int tx = t % THN, ty = t / THN;
  u64 acc[TM][TN/2];
  #pragma unroll
  for (int j=0;j<TNQ;j++){
    float4 c4 = *(const float4*)(gC + tx*TN + j*4);
    #pragma unroll
    for (int i=0;i<TM;i++){ acc[i][2*j]=pack2(c4.x,c4.y); acc[i][2*j+1]=pack2(c4.z,c4.w); }
  }
  #pragma unroll
  for (int k=0;k<K;k++){
    u64 w[TN/2];
    #pragma unroll
    for (int j=0;j<TNQ;j++){
      float4 w4 = *(const float4*)(gW + ((k*TNQ+j)*THN + tx)*4);
      w[2*j]=pack2(w4.x,w4.y); w[2*j+1]=pack2(w4.z,w4.w);
    }
    #pragma unroll
    for (int i=0;i<TM;i++){
      float a = sIn[(ty*TM+i)*LDI + k];
      u64 a2 = pack2(a,a);
      #pragma unroll
      for (int j=0;j<TN/2;j++) acc[i][j]=fma2(a2,w[j],acc[i][j]);
    }
  }
  #pragma unroll
  for (int i=0;i<TM;i++){
    int m = ty*TM+i;
    #pragma unroll
    for (int j=0;j<TNQ;j++){
      float v0,v1,v2,v3;
      unpack2(acc[i][2*j],v0,v1); unpack2(acc[i][2*j+1],v2,v3);
      if (RELU){ v0=fmaxf(v0,0.f); v1=fmaxf(v1,0.f); v2=fmaxf(v2,0.f); v3=fmaxf(v3,0.f); }
      *(float4*)(sOut + m*LDO + tx*TN + 4*j) = make_float4(v0,v1,v2,v3);
    }
  }
}

// Staged layer: weights double-buffered through smem via cp.async.
template<int K,int N,int TN,int TM,int LDI,int LDO,int CK,bool RELU>
__device__ __forceinline__ void gemm_staged(const float* __restrict__ gW,
    const float* __restrict__ gC, const float* sIn, float* sOut,
    float* wBuf, uint32_t wAddr, int t)
{
  constexpr int THN = N/TN, TNQ = TN/4, NC = K/CK;
  constexpr int CHF = CK*N;     // floats per chunk
  constexpr int CV  = CHF/4;    // float4 per chunk
  int tx = t % THN, ty = t / THN;

  // prologue: stage chunk 0 into buffer 0
  if (t < CV) cpa16(wAddr + t*16, gW + t*4);
  asm volatile("cp.async.commit_group;" ::: "memory");

  u64 acc[TM][TN/2];
  #pragma unroll
  for (int j=0;j<TNQ;j++){
    float4 c4 = *(const float4*)(gC + tx*TN + j*4);
    #pragma unroll
    for (int i=0;i<TM;i++){ acc[i][2*j]=pack2(c4.x,c4.y); acc[i][2*j+1]=pack2(c4.z,c4.w); }
  }

  for (int c=0; c<NC; c++){
    __syncthreads();                       // buffer (c+1)&1 free for overwrite
    if (c+1 < NC){
      if (t < CV) cpa16(wAddr + (((c+1)&1)*CHF + t*4)*4, gW + (c+1)*CHF + t*4);
      asm volatile("cp.async.commit_group;" ::: "memory");
      asm volatile("cp.async.wait_group 1;" ::: "memory");
    } else {
      asm volatile("cp.async.wait_group 0;" ::: "memory");
    }
    __syncthreads();                       // chunk c visible to all
    const float* wb = wBuf + (c&1)*CHF;
    #pragma unroll
    for (int kk4=0; kk4<CK/4; kk4++){
      float4 a4[TM];
      #pragma unroll
      for (int i=0;i<TM;i++)
        a4[i] = *(const float4*)(sIn + (ty*TM+i)*LDI + c*CK + kk4*4);
      #pragma unroll
      for (int q=0;q<4;q++){
        int kk = kk4*4+q;
        u64 w[TN/2];
        #pragma unroll
        for (int j=0;j<TNQ;j++){
          float4 w4 = *(const float4*)(wb + ((kk*TNQ+j)*THN + tx)*4);
          w[2*j]=pack2(w4.x,w4.y); w[2*j+1]=pack2(w4.z,w4.w);
        }
        #pragma unroll
        for (int i=0;i<TM;i++){
          float a = (q==0)?a4[i].x:(q==1)?a4[i].y:(q==2)?a4[i].z:a4[i].w;
          u64 a2 = pack2(a,a);
          #pragma unroll
          for (int j=0;j<TN/2;j++) acc[i][j]=fma2(a2,w[j],acc[i][j]);
        }
      }
    }
  }
  #pragma unroll
  for (int i=0;i<TM;i++){
    int m = ty*TM+i;
    #pragma unroll
    for (int j=0;j<TNQ;j++){
      float v0,v1,v2,v3;
      unpack2(acc[i][2*j],v0,v1); unpack2(acc[i][2*j+1],v2,v3);
      if (RELU){ v0=fmaxf(v0,0.f); v1=fmaxf(v1,0.f); v2=fmaxf(v2,0.f); v3=fmaxf(v3,0.f); }
      *(float4*)(sOut + m*LDO + tx*TN + 4*j) = make_float4(v0,v1,v2,v3);
    }
  }
}

__global__ void __launch_bounds__(TPB,1) mlp_kernel(
    const float* __restrict__ pt_fea, const int* __restrict__ pt_ind,
    float* __restrict__ out, int P, int Nn)
{
  extern __shared__ float sm[];
  float* sH2 = sm + SM_H2;
  float* sH3 = sm + SM_H3;
  float* sX  = sm + SM_X;
  float* sH1 = sm + SM_H1;
  float* wBuf = sm + SM_WB;
  int*   sSeg = (int*)(sm + SM_SEG);
  uint32_t wAddr = (uint32_t)__cvta_generic_to_shared(wBuf);

  int t = threadIdx.x;
  int base = blockIdx.x * TILE_M;

  if (t < TILE_M) {
    int p = base + t;
    float x0=0.f,x1=0.f,x2=0.f; int seg=0;
    if (p < P) {
      x0 = pt_fea[p*3+0]; x1 = pt_fea[p*3+1]; x2 = pt_fea[p*3+2];
      int ix = pt_ind[p*3+0], iy = pt_ind[p*3+1], iz = pt_ind[p*3+2];
      int b = p / Nn;
      seg = ((b*GGRID + iz)*GGRID + iy)*GGRID + ix;
    }
    sX[t*4+0]=x0; sX[t*4+1]=x1; sX[t*4+2]=x2; sX[t*4+3]=0.f;
    sSeg[t]=seg;
  }
  __syncthreads();
  gemm_direct<3,  64, L1_TN,4, 4,  68, true>(gF+OFF_A0, gF+OFF_C0, sX , sH1, t);
  __syncthreads();
  gemm_staged<64, 128,L2_TN,4, 68, 132, 8, true>(gF+OFF_A1, gF+OFF_C1, sH1, sH2, wBuf, wAddr, t);
  __syncthreads();
  gemm_staged<128,256,L3_TN,4, 132,260, 8, true>(gF+OFF_A2, gF+OFF_C2, sH2, sH3, wBuf, wAddr, t);
  __syncthreads();

  // Layer 4 (256 -> 64), staged weights, fused scatter-max epilogue
  {
    constexpr int TN = L4_TN, THN = L4_THN, TM = 2, TNQ = TN/4;
    constexpr int K = 256, CK = 32, NC = K/CK;
    constexpr int CHF = CK*64, CV = CHF/4;
    const float* gW = gF + OFF_A3;
    int tx = t % THN, ty = t / THN;

    if (t < CV) cpa16(wAddr + t*16, gW + t*4);
    asm volatile("cp.async.commit_group;" ::: "memory");

    u64 acc[TM][TN/2];
    #pragma unroll
    for (int j=0;j<TNQ;j++){
      float4 c4 = *(const float4*)(gF+OFF_C3 + tx*TN + j*4);
      #pragma unroll
      for (int i=0;i<TM;i++){ acc[i][2*j]=pack2(c4.x,c4.y); acc[i][2*j+1]=pack2(c4.z,c4.w); }
    }
    for (int c=0;c<NC;c++){
      __syncthreads();
      if (c+1 < NC){
        if (t < CV) cpa16(wAddr + (((c+1)&1)*CHF + t*4)*4, gW + (c+1)*CHF + t*4);
        asm volatile("cp.async.commit_group;" ::: "memory");
        asm volatile("cp.async.wait_group 1;" ::: "memory");
      } else {
        asm volatile("cp.async.wait_group 0;" ::: "memory");
      }
      __syncthreads();
      const float* wb = wBuf + (c&1)*CHF;
      #pragma unroll
      for (int kk4=0; kk4<CK/4; kk4++){
        float4 a4[TM];
        #pragma unroll
        for (int i=0;i<TM;i++)
          a4[i] = *(const float4*)(sH3 + (ty*TM+i)*260 + c*CK + kk4*4);
        #pragma unroll
        for (int q=0;q<4;q++){
          int kk = kk4*4+q;
          u64 w[TN/2];
          #pragma unroll
          for (int j=0;j<TNQ;j++){
            float4 w4 = *(const float4*)(wb + ((kk*TNQ+j)*THN + tx)*4);
            w[2*j]=pack2(w4.x,w4.y); w[2*j+1]=pack2(w4.z,w4.w);
          }
          #pragma unroll
          for (int i=0;i<TM;i++){
            float a = (q==0)?a4[i].x:(q==1)?a4[i].y:(q==2)?a4[i].z:a4[i].w;
            u64 a2 = pack2(a,a);
            #pragma unroll
            for (int j=0;j<TN/2;j++) acc[i][j]=fma2(a2,w[j],acc[i][j]);
          }
        }
      }
    }
    #pragma unroll
    for (int i=0;i<TM;i++){
      int m = ty*TM+i; int p = base + m;
      if (p < P){
        float* dst = out + (size_t)sSeg[m]*64 + tx*TN;
        #pragma unroll
        for (int j=0;j<TN/2;j++){
          float lo,hi; unpack2(acc[i][j],lo,hi);
          atomicMaxF(dst+2*j,   lo);
          atomicMaxF(dst+2*j+1, hi);
        }
      }
    }
  }
}

// ---------- launch ----------
extern "C" void kernel_launch(void* const* d_in, const int* in_sizes, int n_in,
                              void* d_out, int out_size)
{
  const float* pt_fea = (const float*)d_in[0];
  const int*   pt_ind = (const int*)d_in[1];
  const float* a[24];
  for (int i=0;i<24;i++) a[i] = (const float*)d_in[2+i];

  int P  = in_sizes[0] / 3;   // 500000
  int Nn = P / 2;             // points per batch (B=2)

  prep_kernel<<<(32768+255)/256, 256>>>(
    a[0],a[1],a[2],a[3], a[4],a[5],a[6],a[7],
    a[8],a[9],a[10],a[11], a[12],a[13],a[14],a[15],
    a[16],a[17], a[18],a[19], a[20],a[21], a[22],a[23]);

  int n16 = out_size / 4;
  init_kernel<<<(n16+255)/256, 256>>>((uint4*)d_out, n16);

  cudaFuncSetAttribute(mlp_kernel, cudaFuncAttributeMaxDynamicSharedMemorySize, SM_TOTALF*4);
  int blocks = (P + TILE_M - 1) / TILE_M;
  mlp_kernel<<<blocks, TPB, SM_TOTALF*4>>>(pt_fea, pt_ind, (float*)d_out, P, Nn);

  finalize_kernel<<<(n16+255)/256, 256>>>((uint4*)d_out, n16);
}